// round 9
// baseline (speedup 1.0000x reference)
#include <cuda_runtime.h>
#include <math.h>

// BidirectionalALiBi: out[h, i, j] = |j - i| * c
//   c = alpha[h] if (i==0 || j==0), gamma[h] if j>i, beta[h] if j<i, 0 on diag.
//
// Branch-free identity: with p=(g+b)/2, m=(g-b)/2, d=j-i (float):
//   |d|*p + d*m  =  d*g (d>0) | |d|*b (d<0) | 0 (d==0)
// Row i==0 -> set g=b=alpha. Column j==0 -> one patched element: i*alpha.
//
// R8 changes vs R5:
//  * persistent grid-stride over row-groups (single wave, no wave-transition
//    overhead: grid was 4096 CTAs = ~14 waves -> now 148*4 CTAs = 1 wave)
//  * __stcs evict-first streaming stores (output is write-once, 2x L2 size)
//  * occupancy cap 2 -> 4 CTAs/SM for deeper store MLP

template<int LOGS>
__global__ __launch_bounds__(512, 4)
void alibi_persist_kernel(const float* __restrict__ alpha,
                          const float* __restrict__ beta,
                          const float* __restrict__ gamma,
                          float* __restrict__ out,
                          int ngroups)              // H*S/8 row-groups
{
    constexpr int S     = 1 << LOGS;
    constexpr int VROW  = S >> 2;        // float4 per row
    constexpr int NITER = VROW >> 6;     // 8 when S=2048 (64 threads/row)

    const int tid     = threadIdx.x;
    const int r_local = tid >> 6;                 // 0..7
    const int trow    = tid & 63;                 // 0..63 within row
    const bool patch_j0 = (trow == 0);

    for (int grp = blockIdx.x; grp < ngroups; grp += gridDim.x) {
        const int row = (grp << 3) + r_local;
        const int h   = row >> LOGS;              // rows in a group share h
        const int i   = row & (S - 1);

        const float a = __ldg(alpha + h);
        float b = __ldg(beta  + h);
        float g = __ldg(gamma + h);
        if (i == 0) { g = a; b = a; }             // whole-row edge override

        const float p  = 0.5f * (g + b);
        const float m  = 0.5f * (g - b);
        const float fi = (float)i;
        const float d0 = (float)(trow << 2) - fi; // d at (v=0, k=0)

        float4* __restrict__ orow =
            reinterpret_cast<float4*>(out) + (size_t)row * VROW + trow;

        {   // first iteration carries the j==0 column patch
            float4 w;
            w.x = patch_j0 ? fi * a
                           : fmaf(fabsf(d0        ), p, (d0        ) * m);
            w.y = fmaf(fabsf(d0 + 1.0f), p, (d0 + 1.0f) * m);
            w.z = fmaf(fabsf(d0 + 2.0f), p, (d0 + 2.0f) * m);
            w.w = fmaf(fabsf(d0 + 3.0f), p, (d0 + 3.0f) * m);
            __stcs(orow, w);                      // STG.E.128 evict-first
        }
#pragma unroll
        for (int v = 1; v < NITER; v++) {
            const float dv = d0 + (float)(v << 8);
            float4 w;
            w.x = fmaf(fabsf(dv        ), p, (dv        ) * m);
            w.y = fmaf(fabsf(dv + 1.0f), p, (dv + 1.0f) * m);
            w.z = fmaf(fabsf(dv + 2.0f), p, (dv + 2.0f) * m);
            w.w = fmaf(fabsf(dv + 3.0f), p, (dv + 3.0f) * m);
            __stcs(orow + ((size_t)v << 6), w);   // warp-contiguous 512B
        }
    }
}

// Generic fallback for arbitrary S (correct, not perf-critical).
__global__ void alibi_scalar_kernel(const float* __restrict__ alpha,
                                    const float* __restrict__ beta,
                                    const float* __restrict__ gamma,
                                    float* __restrict__ out,
                                    int S, int H)
{
    const long long total = (long long)H * S * S;
    for (long long idx = (long long)blockIdx.x * blockDim.x + threadIdx.x;
         idx < total;
         idx += (long long)gridDim.x * blockDim.x)
    {
        const int j = (int)(idx % S);
        long long r = idx / S;
        const int i = (int)(r % S);
        const int h = (int)(r / S);
        float c = (j > i) ? __ldg(gamma + h) : __ldg(beta + h);
        c = (i == 0 || j == 0) ? __ldg(alpha + h) : c;
        out[idx] = fabsf((float)(j - i)) * c;
    }
}

extern "C" void kernel_launch(void* const* d_in, const int* in_sizes, int n_in,
                              void* d_out, int out_size)
{
    const float* alpha = (const float*)d_in[0];
    const float* beta  = (const float*)d_in[1];
    const float* gamma = (const float*)d_in[2];
    const int H = in_sizes[0];
    float* out = (float*)d_out;

    // Derive S from out_size = H*S*S (seq_len lives on device; can't sync-read
    // under graph capture).
    long long per_h = (long long)out_size / H;
    long long s = (long long)(sqrt((double)per_h));
    while (s * s < per_h) s++;
    while (s * s > per_h) s--;
    const int S = (int)s;

    const int SM_COUNT = 148;
    if (S == 2048 || S == 1024 || S == 4096) {
        const int ngroups = (H * S) >> 3;         // 8 rows per group
        int grid = SM_COUNT * 4;                  // single wave at occ=4
        if (grid > ngroups) grid = ngroups;
        if (S == 2048)
            alibi_persist_kernel<11><<<grid, 512>>>(alpha, beta, gamma, out, ngroups);
        else if (S == 1024)
            alibi_persist_kernel<10><<<grid, 512>>>(alpha, beta, gamma, out, ngroups);
        else
            alibi_persist_kernel<12><<<grid, 512>>>(alpha, beta, gamma, out, ngroups);
    } else {
        const long long total = (long long)H * S * S;
        int blocks = (int)((total + 255) / 256);
        if (blocks > SM_COUNT * 32 * 4) blocks = SM_COUNT * 32 * 4;
        alibi_scalar_kernel<<<blocks, 256>>>(alpha, beta, gamma, out, S, H);
    }
}

// round 10
// speedup vs baseline: 1.1197x; 1.1197x over previous
#include <cuda_runtime.h>
#include <math.h>

// BidirectionalALiBi: out[h, i, j] = |j - i| * c
//   c = alpha[h] if (i==0 || j==0), gamma[h] if j>i, beta[h] if j<i, 0 on diag.
//
// Branch-free identity: with p=(g+b)/2, m=(g-b)/2, d=j-i (float):
//   |d|*p + d*m  =  d*g (d>0) | |d|*b (d<0) | 0 (d==0)
// Row i==0 -> set g=b=alpha. Column j==0 -> one patched element: i*alpha.
//
// R9 lesson: persistent 592-CTA grid creates a ~1/7 load-imbalance tail
// (occ 81->72%, +5us). Reverting to the 4096-CTA launch (HW scheduler
// balances small CTAs perfectly). Single isolated change vs the 37.95us
// best: __stcs evict-first streaming stores (output is write-once, 2x L2).

template<int LOGS>
__global__ __launch_bounds__(512)
void alibi_tiled_kernel(const float* __restrict__ alpha,
                        const float* __restrict__ beta,
                        const float* __restrict__ gamma,
                        float* __restrict__ out)
{
    constexpr int S     = 1 << LOGS;
    constexpr int VROW  = S >> 2;        // float4 per row
    constexpr int NITER = VROW >> 6;     // 8 when S=2048 (64 threads/row)

    const int tid     = threadIdx.x;
    const int r_local = tid >> 6;                 // 0..7
    const int trow    = tid & 63;                 // 0..63 within row
    const int row     = (blockIdx.x << 3) + r_local;
    const int h       = row >> LOGS;              // 8 rows/block share h
    const int i       = row & (S - 1);

    const float a = __ldg(alpha + h);
    float b = __ldg(beta  + h);
    float g = __ldg(gamma + h);
    if (i == 0) { g = a; b = a; }                 // whole-row edge override

    const float p  = 0.5f * (g + b);
    const float m  = 0.5f * (g - b);
    const float fi = (float)i;
    const float d0 = (float)(trow << 2) - fi;     // d at (v=0, k=0)
    const bool  patch_j0 = (trow == 0);

    float4* __restrict__ orow =
        reinterpret_cast<float4*>(out) + (size_t)row * VROW + trow;

    {   // first iteration carries the j==0 column patch
        float4 w;
        w.x = patch_j0 ? fi * a
                       : fmaf(fabsf(d0        ), p, (d0        ) * m);
        w.y = fmaf(fabsf(d0 + 1.0f), p, (d0 + 1.0f) * m);
        w.z = fmaf(fabsf(d0 + 2.0f), p, (d0 + 2.0f) * m);
        w.w = fmaf(fabsf(d0 + 3.0f), p, (d0 + 3.0f) * m);
        __stcs(orow, w);                          // STG.E.128 evict-first
    }
#pragma unroll
    for (int v = 1; v < NITER; v++) {
        const float dv = d0 + (float)(v << 8);    // stride 64 float4 = 1KB
        float4 w;
        w.x = fmaf(fabsf(dv        ), p, (dv        ) * m);
        w.y = fmaf(fabsf(dv + 1.0f), p, (dv + 1.0f) * m);
        w.z = fmaf(fabsf(dv + 2.0f), p, (dv + 2.0f) * m);
        w.w = fmaf(fabsf(dv + 3.0f), p, (dv + 3.0f) * m);
        __stcs(orow + ((size_t)v << 6), w);       // warp-contiguous 512B
    }
}

// Generic fallback for arbitrary S (correct, not perf-critical).
__global__ void alibi_scalar_kernel(const float* __restrict__ alpha,
                                    const float* __restrict__ beta,
                                    const float* __restrict__ gamma,
                                    float* __restrict__ out,
                                    int S, int H)
{
    const long long total = (long long)H * S * S;
    for (long long idx = (long long)blockIdx.x * blockDim.x + threadIdx.x;
         idx < total;
         idx += (long long)gridDim.x * blockDim.x)
    {
        const int j = (int)(idx % S);
        long long r = idx / S;
        const int i = (int)(r % S);
        const int h = (int)(r / S);
        float c = (j > i) ? __ldg(gamma + h) : __ldg(beta + h);
        c = (i == 0 || j == 0) ? __ldg(alpha + h) : c;
        out[idx] = fabsf((float)(j - i)) * c;
    }
}

extern "C" void kernel_launch(void* const* d_in, const int* in_sizes, int n_in,
                              void* d_out, int out_size)
{
    const float* alpha = (const float*)d_in[0];
    const float* beta  = (const float*)d_in[1];
    const float* gamma = (const float*)d_in[2];
    const int H = in_sizes[0];
    float* out = (float*)d_out;

    // Derive S from out_size = H*S*S (seq_len lives on device; can't sync-read
    // under graph capture).
    long long per_h = (long long)out_size / H;
    long long s = (long long)(sqrt((double)per_h));
    while (s * s < per_h) s++;
    while (s * s > per_h) s--;
    const int S = (int)s;

    if (S == 2048) {
        alibi_tiled_kernel<11><<<(H * S) >> 3, 512>>>(alpha, beta, gamma, out);
    } else if (S == 1024) {
        alibi_tiled_kernel<10><<<(H * S) >> 3, 512>>>(alpha, beta, gamma, out);
    } else if (S == 4096) {
        alibi_tiled_kernel<12><<<(H * S) >> 3, 512>>>(alpha, beta, gamma, out);
    } else {
        const long long total = (long long)H * S * S;
        int blocks = (int)((total + 255) / 256);
        if (blocks > 148 * 32 * 4) blocks = 148 * 32 * 4;
        alibi_scalar_kernel<<<blocks, 256>>>(alpha, beta, gamma, out, S, H);
    }
}